// round 2
// baseline (speedup 1.0000x reference)
#include <cuda_runtime.h>

#define S_LEN 8192
#define F_DIM 128
#define TI 4
#define NTHREADS 256

// sizes (floats)
#define SA_F 16896   // max(Qt 128*128, QMs 128*129, At3 128*132)
#define SB_F 16512   // max(M 128*128, Ks 128*129, Vs 128*128, WvT 128*128)
#define SS_F 4224    // max(scores 128*33, attnT 32*129)
#define SMEM_BYTES ((SA_F + SB_F + SS_F) * 4)

// scratch: M = scale * Wq^T @ Wk  (128x128)
__device__ float g_M[F_DIM * F_DIM];

__global__ void compute_M_kernel(const float* __restrict__ Wq,
                                 const float* __restrict__ Wk) {
    int j = blockIdx.x;   // 0..127
    int l = threadIdx.x;  // 0..127
    float acc = 0.f;
#pragma unroll 8
    for (int f = 0; f < F_DIM; ++f)
        acc += Wq[f * F_DIM + j] * Wk[f * F_DIM + l];
    g_M[j * F_DIM + l] = acc * 0.08838834764831845f;  // 1/sqrt(128)
}

__global__ __launch_bounds__(NTHREADS, 1)
void fused_attn_kernel(const float* __restrict__ Q,
                       const float* __restrict__ K,
                       const float* __restrict__ V,
                       const float* __restrict__ Wv,
                       float* __restrict__ Out) {
    extern __shared__ float sm[];
    float* sA = sm;                  // big buffer A
    float* sB = sm + SA_F;           // big buffer B
    float* sS = sm + SA_F + SB_F;    // scores / attnT

    const int t  = threadIdx.x;
    const int i0 = blockIdx.x * TI;

    const int rg = t >> 4;     // 0..15 row group
    const int cg = t & 15;     // 0..15 col group
    const int r0 = rg * 8;     // rows r0..r0+7  (r = it*32 + b)
    const int myIt = r0 >> 5;  // same for all 8 rows (8 | 32)

    // ================= P0: Qt -> sA[j*128+r], M -> sB[j*128+l] =================
    {
        const int r  = t >> 1;
        const int b  = r & 31, it = r >> 5;
        const int jh = (t & 1) * 64;
        const float* qrow = Q + ((size_t)b * S_LEN + (i0 + it)) * F_DIM + jh;
#pragma unroll
        for (int u = 0; u < 16; ++u) {
            float4 x = *(const float4*)(qrow + 4 * u);
            int j = jh + 4 * u;
            sA[(j + 0) * 128 + r] = x.x;
            sA[(j + 1) * 128 + r] = x.y;
            sA[(j + 2) * 128 + r] = x.z;
            sA[(j + 3) * 128 + r] = x.w;
        }
        const float4* gm4 = (const float4*)g_M;
        float4* sb4 = (float4*)sB;
#pragma unroll
        for (int u = 0; u < 16; ++u)
            sb4[u * 256 + t] = gm4[u * 256 + t];
    }
    __syncthreads();

    // ================= P1: QM[r][l] = sum_j Qt[j][r]*M[j][l] =================
    float acc[8][8];
#pragma unroll
    for (int u = 0; u < 8; ++u)
#pragma unroll
        for (int c = 0; c < 8; ++c) acc[u][c] = 0.f;

#pragma unroll 2
    for (int kk = 0; kk < 128; ++kk) {
        float a[8];
        float4 a0 = *(const float4*)&sA[kk * 128 + r0];
        float4 a1 = *(const float4*)&sA[kk * 128 + r0 + 4];
        a[0]=a0.x; a[1]=a0.y; a[2]=a0.z; a[3]=a0.w;
        a[4]=a1.x; a[5]=a1.y; a[6]=a1.z; a[7]=a1.w;
        float bb[8];
#pragma unroll
        for (int vv = 0; vv < 4; ++vv) {
            float2 bv = *(const float2*)&sB[kk * 128 + cg * 2 + 32 * vv];
            bb[2*vv] = bv.x; bb[2*vv+1] = bv.y;
        }
#pragma unroll
        for (int u = 0; u < 8; ++u)
#pragma unroll
            for (int c = 0; c < 8; ++c)
                acc[u][c] += a[u] * bb[c];
    }
    __syncthreads();

    // ====== QM -> sA[r*129+l] (padded), K tile -> sB[rr*129+l] (padded) ======
#pragma unroll
    for (int u = 0; u < 8; ++u)
#pragma unroll
        for (int c = 0; c < 8; ++c) {
            int col = cg * 2 + 32 * (c >> 1) + (c & 1);
            sA[(r0 + u) * 129 + col] = acc[u][c];
        }
    {
        const int rr = t >> 1;
        const int d = rr & 31, it = rr >> 5;
        const int lh = (t & 1) * 64;
        const float* krow = K + ((size_t)d * S_LEN + (i0 + it)) * F_DIM + lh;
#pragma unroll
        for (int u = 0; u < 16; ++u) {
            float4 x = *(const float4*)(krow + 4 * u);
            int l = lh + 4 * u;
            sB[rr * 129 + l + 0] = x.x;
            sB[rr * 129 + l + 1] = x.y;
            sB[rr * 129 + l + 2] = x.z;
            sB[rr * 129 + l + 3] = x.w;
        }
    }
    __syncthreads();

    // ================= P2: scores[it][b][d] = QM[r_b] . K[r_d] =================
    {
        const int it = t >> 6;
        const int bg = (t >> 3) & 7;
        const int dg = t & 7;
        const int rb = it * 32 + bg * 4;
        const int rd = it * 32 + dg * 4;
        float sc[4][4];
#pragma unroll
        for (int u = 0; u < 4; ++u)
#pragma unroll
            for (int vv = 0; vv < 4; ++vv) sc[u][vv] = 0.f;
#pragma unroll 4
        for (int l = 0; l < 128; ++l) {
            float qa[4], kb[4];
#pragma unroll
            for (int u = 0; u < 4; ++u)  qa[u]  = sA[(rb + u) * 129 + l];
#pragma unroll
            for (int vv = 0; vv < 4; ++vv) kb[vv] = sB[(rd + vv) * 129 + l];
#pragma unroll
            for (int u = 0; u < 4; ++u)
#pragma unroll
                for (int vv = 0; vv < 4; ++vv)
                    sc[u][vv] += qa[u] * kb[vv];
        }
#pragma unroll
        for (int u = 0; u < 4; ++u)
#pragma unroll
            for (int vv = 0; vv < 4; ++vv)
                sS[(it * 32 + bg * 4 + u) * 33 + dg * 4 + vv] = sc[u][vv];
    }
    __syncthreads();

    // ====== V tile -> sB[rr*128+f] (vector) ; softmax over d (lane = d) ======
    {
        const int rr = t >> 1;
        const int d = rr & 31, it = rr >> 5;
        const int fh = (t & 1) * 64;
        const float* vrow = V + ((size_t)d * S_LEN + (i0 + it)) * F_DIM + fh;
        float4* dst = (float4*)&sB[rr * 128 + fh];
#pragma unroll
        for (int u = 0; u < 16; ++u)
            dst[u] = *(const float4*)(vrow + 4 * u);
    }
    float att[16];
    {
        const int lane = t & 31;
        const int w = t >> 5;
#pragma unroll
        for (int g = 0; g < 16; ++g) {
            int gid = w * 16 + g;                  // = it*32 + b
            float s = sS[gid * 33 + lane];         // lane = d
            float m = s;
#pragma unroll
            for (int off = 16; off > 0; off >>= 1)
                m = fmaxf(m, __shfl_xor_sync(0xffffffffu, m, off));
            float e = __expf(s - m);
            float sum = e;
#pragma unroll
            for (int off = 16; off > 0; off >>= 1)
                sum += __shfl_xor_sync(0xffffffffu, sum, off);
            att[g] = e / sum;
        }
    }
    __syncthreads();
    {   // attnT[d][r] with pad-129, conflict-free writes
        const int lane = t & 31;
        const int w = t >> 5;
#pragma unroll
        for (int g = 0; g < 16; ++g)
            sS[lane * 129 + (w * 16 + g)] = att[g];
    }
    __syncthreads();

    // ======== P4: raw[r][c] = sum_d attnT[d][r] * V[(it*32+d)][c] ========
#pragma unroll
    for (int u = 0; u < 8; ++u)
#pragma unroll
        for (int c = 0; c < 8; ++c) acc[u][c] = 0.f;
#pragma unroll 2
    for (int dd = 0; dd < 32; ++dd) {
        float a[8];
#pragma unroll
        for (int u = 0; u < 8; ++u) a[u] = sS[dd * 129 + r0 + u];
        float bb[8];
#pragma unroll
        for (int vv = 0; vv < 4; ++vv) {
            float2 bv = *(const float2*)&sB[(myIt * 32 + dd) * 128 + cg * 2 + 32 * vv];
            bb[2*vv] = bv.x; bb[2*vv+1] = bv.y;
        }
#pragma unroll
        for (int u = 0; u < 8; ++u)
#pragma unroll
            for (int c = 0; c < 8; ++c)
                acc[u][c] += a[u] * bb[c];
    }
    __syncthreads();

    // ====== raw -> sA[g*132+r] (transposed, padded) ; WvT -> sB[g*128+c] ======
#pragma unroll
    for (int u = 0; u < 8; ++u)
#pragma unroll
        for (int c = 0; c < 8; ++c) {
            int col = cg * 2 + 32 * (c >> 1) + (c & 1);
            sA[col * 132 + r0 + u] = acc[u][c];
        }
    {
        const int cidx = t >> 1;            // Wv row = output feature
        const int gh = (t & 1) * 64;
        const float* wrow = Wv + cidx * F_DIM + gh;
#pragma unroll
        for (int u = 0; u < 16; ++u) {
            float4 x = *(const float4*)(wrow + 4 * u);
            int g = gh + 4 * u;
            sB[(g + 0) * 128 + cidx] = x.x;
            sB[(g + 1) * 128 + cidx] = x.y;
            sB[(g + 2) * 128 + cidx] = x.z;
            sB[(g + 3) * 128 + cidx] = x.w;
        }
    }
    __syncthreads();

    // ========= P5: out[r][c] = sum_g raw[r][g] * Wv[c][g] =========
#pragma unroll
    for (int u = 0; u < 8; ++u)
#pragma unroll
        for (int c = 0; c < 8; ++c) acc[u][c] = 0.f;
#pragma unroll 2
    for (int g = 0; g < 128; ++g) {
        float a[8];
        float4 a0 = *(const float4*)&sA[g * 132 + r0];
        float4 a1 = *(const float4*)&sA[g * 132 + r0 + 4];
        a[0]=a0.x; a[1]=a0.y; a[2]=a0.z; a[3]=a0.w;
        a[4]=a1.x; a[5]=a1.y; a[6]=a1.z; a[7]=a1.w;
        float bb[8];
#pragma unroll
        for (int vv = 0; vv < 4; ++vv) {
            float2 bv = *(const float2*)&sB[g * 128 + cg * 2 + 32 * vv];
            bb[2*vv] = bv.x; bb[2*vv+1] = bv.y;
        }
#pragma unroll
        for (int u = 0; u < 8; ++u)
#pragma unroll
            for (int c = 0; c < 8; ++c)
                acc[u][c] += a[u] * bb[c];
    }

    // ========= store out (float2, coalesced-ish) =========
#pragma unroll
    for (int u = 0; u < 8; ++u) {
        int r = r0 + u;
        int b = r & 31, it = r >> 5;
        float* orow = Out + ((size_t)b * S_LEN + (i0 + it)) * F_DIM;
#pragma unroll
        for (int vv = 0; vv < 4; ++vv) {
            float2 st;
            st.x = acc[u][2 * vv];
            st.y = acc[u][2 * vv + 1];
            *(float2*)&orow[cg * 2 + 32 * vv] = st;
        }
    }
}

extern "C" void kernel_launch(void* const* d_in, const int* in_sizes, int n_in,
                              void* d_out, int out_size) {
    const float* q  = (const float*)d_in[0];
    const float* k  = (const float*)d_in[1];
    const float* v  = (const float*)d_in[2];
    const float* Wq = (const float*)d_in[3];
    const float* Wk = (const float*)d_in[4];
    const float* Wv = (const float*)d_in[5];
    float* out = (float*)d_out;

    // M = scale * Wq^T @ Wk (tiny; runs every launch, deterministic)
    compute_M_kernel<<<F_DIM, F_DIM>>>(Wq, Wk);

    cudaFuncSetAttribute(fused_attn_kernel,
                         cudaFuncAttributeMaxDynamicSharedMemorySize, SMEM_BYTES);
    fused_attn_kernel<<<S_LEN / TI, NTHREADS, SMEM_BYTES>>>(q, k, v, Wv, out);
}

// round 4
// speedup vs baseline: 1.9415x; 1.9415x over previous
#include <cuda_runtime.h>
#include <cuda_bf16.h>
#include <cstdint>

#define S_LEN 8192
#define FD 128
#define TI 4
#define NT 256
#define STB 272   // bytes per smem row (136 bf16 elems; conflict-free fragment access)

// ---- smem layout (byte offsets), each buffer 128*272 = 34816 B ----
#define A_HI  0u
#define A_LO  34816u
#define B1_HI 69632u
#define B1_LO 104448u
#define B2_HI 139264u
#define B2_LO 174080u
#define SMEM_BYTES 208896

// ---------------- helpers ----------------
__device__ __forceinline__ uint32_t lds_pair(const char* sm, uint32_t off, int row, int col) {
    return *(const uint32_t*)(sm + off + row * STB + col * 2);
}
__device__ __forceinline__ void sts_pair(char* sm, uint32_t off, int row, int col, uint32_t v) {
    *(uint32_t*)(sm + off + row * STB + col * 2) = v;
}
// split (a,b) fp32 -> packed bf16x2 hi and lo (residual)
__device__ __forceinline__ void split2(float a, float b, uint32_t& hi, uint32_t& lo) {
    __nv_bfloat16 ha = __float2bfloat16(a), hb = __float2bfloat16(b);
    __nv_bfloat162 H; H.x = ha; H.y = hb;
    hi = *reinterpret_cast<uint32_t*>(&H);
    __nv_bfloat162 L = __floats2bfloat162_rn(a - __bfloat162float(ha), b - __bfloat162float(hb));
    lo = *reinterpret_cast<uint32_t*>(&L);
}

__device__ __forceinline__ void mma16816(float* d, const uint32_t* a, uint32_t b0, uint32_t b1) {
    asm volatile(
        "mma.sync.aligned.m16n8k16.row.col.f32.bf16.bf16.f32 "
        "{%0,%1,%2,%3}, {%4,%5,%6,%7}, {%8,%9}, {%0,%1,%2,%3};"
        : "+f"(d[0]), "+f"(d[1]), "+f"(d[2]), "+f"(d[3])
        : "r"(a[0]), "r"(a[1]), "r"(a[2]), "r"(a[3]), "r"(b0), "r"(b1));
}

// ---------------- precomputed operand images (bf16 hi/lo, stride-136 layout) ----------------
__device__ __align__(16) __nv_bfloat16 g_Mt_hi[128 * 136];
__device__ __align__(16) __nv_bfloat16 g_Mt_lo[128 * 136];
__device__ __align__(16) __nv_bfloat16 g_Wv_hi[128 * 136];
__device__ __align__(16) __nv_bfloat16 g_Wv_lo[128 * 136];

// Mt[n][k] = scale * sum_l Wq[l][k]*Wk[l][n]   (B operand of G1)
// Wv image: B operand of G4 is Wv[c][g] natural row-major.
__global__ void prep_kernel(const float* __restrict__ Wq, const float* __restrict__ Wk,
                            const float* __restrict__ Wv) {
    int n = blockIdx.x, k = threadIdx.x;
    float acc = 0.f;
#pragma unroll 8
    for (int l = 0; l < FD; ++l)
        acc += Wq[l * FD + k] * Wk[l * FD + n];
    acc *= 0.08838834764831845f;  // 1/sqrt(128)
    int idx = n * 136 + k;
    __nv_bfloat16 h = __float2bfloat16(acc);
    g_Mt_hi[idx] = h;
    g_Mt_lo[idx] = __float2bfloat16(acc - __bfloat162float(h));
    float wv = Wv[n * FD + k];
    h = __float2bfloat16(wv);
    g_Wv_hi[idx] = h;
    g_Wv_lo[idx] = __float2bfloat16(wv - __bfloat162float(h));
}

// full 128x128x128 GEMM, warp tile 32m x 64n, bf16x3
__device__ __forceinline__ void gemm_full(const char* sm, float acc[2][8][4],
                                          int mBase, int nBase, int lane,
                                          uint32_t aH, uint32_t aL, uint32_t bH, uint32_t bL) {
    const int g = lane >> 2, tg = lane & 3;
#pragma unroll 1
    for (int pass = 0; pass < 3; ++pass) {
        uint32_t aOff = (pass == 2) ? aL : aH;
        uint32_t bOff = (pass == 1) ? bL : bH;
#pragma unroll
        for (int ks = 0; ks < 8; ++ks) {
            int kc = ks * 16 + tg * 2;
            uint32_t a[2][4];
#pragma unroll
            for (int mt = 0; mt < 2; ++mt) {
                int r = mBase + mt * 16 + g;
                a[mt][0] = lds_pair(sm, aOff, r, kc);
                a[mt][1] = lds_pair(sm, aOff, r + 8, kc);
                a[mt][2] = lds_pair(sm, aOff, r, kc + 8);
                a[mt][3] = lds_pair(sm, aOff, r + 8, kc + 8);
            }
#pragma unroll
            for (int nt = 0; nt < 8; ++nt) {
                int nr = nBase + nt * 8 + g;
                uint32_t b0 = lds_pair(sm, bOff, nr, kc);
                uint32_t b1 = lds_pair(sm, bOff, nr, kc + 8);
                mma16816(acc[0][nt], a[0], b0, b1);
                mma16816(acc[1][nt], a[1], b0, b1);
            }
        }
    }
}

// load a 128x128 fp32 tile (row r = it*32+b), split, store hi/lo stride-136
__device__ __forceinline__ void load_split(const float* __restrict__ base, uint32_t i0,
                                           char* sm, uint32_t dHi, uint32_t dLo, int t) {
    int r = t >> 1;
    int h4 = (t & 1) * 4;
    const float* row = base + ((size_t)(r & 31) * S_LEN + (i0 + (r >> 5))) * FD;
#pragma unroll
    for (int u = 0; u < 16; ++u) {
        int col = 8 * u + h4;
        float4 x = *(const float4*)(row + col);
        uint32_t h0, l0, h1, l1;
        split2(x.x, x.y, h0, l0);
        split2(x.z, x.w, h1, l1);
        sts_pair(sm, dHi, r, col, h0);
        sts_pair(sm, dHi, r, col + 2, h1);
        sts_pair(sm, dLo, r, col, l0);
        sts_pair(sm, dLo, r, col + 2, l1);
    }
}

// one bf16 pass of G3 (attn @ Vt), attn A-fragments in registers
__device__ __forceinline__ void g3_pass(const char* sm, float acc3[16][4],
                                        const uint32_t a3[2][4], uint32_t bOff,
                                        int it, int lane) {
    const int g = lane >> 2, tg = lane & 3;
#pragma unroll
    for (int ks = 0; ks < 2; ++ks) {
        int kc = it * 32 + ks * 16 + tg * 2;
#pragma unroll
        for (int nt = 0; nt < 16; ++nt) {
            int nr = nt * 8 + g;
            uint32_t b0 = lds_pair(sm, bOff, nr, kc);
            uint32_t b1 = lds_pair(sm, bOff, nr, kc + 8);
            mma16816(acc3[nt], a3[ks], b0, b1);
        }
    }
}

__global__ __launch_bounds__(NT, 1)
void fused_attn_mma(const float* __restrict__ Q, const float* __restrict__ K,
                    const float* __restrict__ V, float* __restrict__ Out) {
    extern __shared__ char sm[];
    const int t = threadIdx.x, lane = t & 31, w = t >> 5;
    const int g = lane >> 2, tg = lane & 3;
    const uint32_t i0 = blockIdx.x * TI;

    // ---- P0: Mt -> B1, Q -> A, K -> B2 ----
    {
        const uint4* mh = (const uint4*)g_Mt_hi;
        const uint4* ml = (const uint4*)g_Mt_lo;
        uint4* dh = (uint4*)(sm + B1_HI);
        uint4* dl = (uint4*)(sm + B1_LO);
#pragma unroll
        for (int u = 0; u < 8; ++u) {
            int i = u * NT + t;
            if (i < 2176) { dh[i] = mh[i]; dl[i] = ml[i]; }
        }
        {   // tail (2176 = 8*256+128): handled by guard above? 8*256=2048 <2176 -> need 9th
            int i = 8 * NT + t;
            if (i < 2176) { dh[i] = mh[i]; dl[i] = ml[i]; }
        }
    }
    load_split(Q, i0, sm, A_HI, A_LO, t);
    load_split(K, i0, sm, B2_HI, B2_LO, t);
    __syncthreads();

    // ---- G1: QM = Q @ Mt^T ----
    const int mB = (w >> 1) * 32, nB = (w & 1) * 64;
    float acc[2][8][4];
#pragma unroll
    for (int mt = 0; mt < 2; ++mt)
#pragma unroll
        for (int nt = 0; nt < 8; ++nt)
#pragma unroll
            for (int j = 0; j < 4; ++j) acc[mt][nt][j] = 0.f;
    gemm_full(sm, acc, mB, nB, lane, A_HI, A_LO, B1_HI, B1_LO);
    __syncthreads();

    // ---- P1: QM frags -> A (hi/lo); V^T -> B1 ----
#pragma unroll
    for (int mt = 0; mt < 2; ++mt)
#pragma unroll
        for (int nt = 0; nt < 8; ++nt) {
            int r = mB + mt * 16 + g, c = nB + nt * 8 + tg * 2;
            uint32_t h, l;
            split2(acc[mt][nt][0], acc[mt][nt][1], h, l);
            sts_pair(sm, A_HI, r, c, h);
            sts_pair(sm, A_LO, r, c, l);
            split2(acc[mt][nt][2], acc[mt][nt][3], h, l);
            sts_pair(sm, A_HI, r + 8, c, h);
            sts_pair(sm, A_LO, r + 8, c, l);
        }
    {   // V transpose: B1[f][kr] = V row kr, element f
        int kr = t >> 1;
        int fh = (t & 1) * 64;
        const float4* vrow = (const float4*)(V + ((size_t)(kr & 31) * S_LEN + (i0 + (kr >> 5))) * FD + fh);
#pragma unroll
        for (int u = 0; u < 16; ++u) {
            float4 x = vrow[u];
            int f0 = fh + 4 * u;
            float xs[4] = {x.x, x.y, x.z, x.w};
#pragma unroll
            for (int j = 0; j < 4; ++j) {
                __nv_bfloat16 h = __float2bfloat16(xs[j]);
                __nv_bfloat16 l = __float2bfloat16(xs[j] - __bfloat162float(h));
                *(__nv_bfloat16*)(sm + B1_HI + (f0 + j) * STB + kr * 2) = h;
                *(__nv_bfloat16*)(sm + B1_LO + (f0 + j) * STB + kr * 2) = l;
            }
        }
    }
    __syncthreads();

    // ---- G2: diagonal scores (warp: 16 rows x 32 cols) ----
    const int it = w >> 1;
    const int mB2 = it * 32 + (w & 1) * 16;
    const int nB2 = it * 32;
    float sc[4][4];
#pragma unroll
    for (int nt = 0; nt < 4; ++nt)
#pragma unroll
        for (int j = 0; j < 4; ++j) sc[nt][j] = 0.f;
#pragma unroll 1
    for (int pass = 0; pass < 3; ++pass) {
        uint32_t aOff = (pass == 2) ? A_LO : A_HI;
        uint32_t bOff = (pass == 1) ? B2_LO : B2_HI;
#pragma unroll
        for (int ks = 0; ks < 8; ++ks) {
            int kc = ks * 16 + tg * 2;
            uint32_t a[4];
            int r = mB2 + g;
            a[0] = lds_pair(sm, aOff, r, kc);
            a[1] = lds_pair(sm, aOff, r + 8, kc);
            a[2] = lds_pair(sm, aOff, r, kc + 8);
            a[3] = lds_pair(sm, aOff, r + 8, kc + 8);
#pragma unroll
            for (int nt = 0; nt < 4; ++nt) {
                int nr = nB2 + nt * 8 + g;
                uint32_t b0 = lds_pair(sm, bOff, nr, kc);
                uint32_t b1 = lds_pair(sm, bOff, nr, kc + 8);
                mma16816(sc[nt], a, b0, b1);
            }
        }
    }

    // ---- softmax over the 32 cols (rows g and g+8 of this warp strip) ----
    {
        float mx0 = -1e30f, mx1 = -1e30f;
#pragma unroll
        for (int nt = 0; nt < 4; ++nt) {
            mx0 = fmaxf(mx0, fmaxf(sc[nt][0], sc[nt][1]));
            mx1 = fmaxf(mx1, fmaxf(sc[nt][2], sc[nt][3]));
        }
        mx0 = fmaxf(mx0, __shfl_xor_sync(0xffffffffu, mx0, 1));
        mx0 = fmaxf(mx0, __shfl_xor_sync(0xffffffffu, mx0, 2));
        mx1 = fmaxf(mx1, __shfl_xor_sync(0xffffffffu, mx1, 1));
        mx1 = fmaxf(mx1, __shfl_xor_sync(0xffffffffu, mx1, 2));
        float s0 = 0.f, s1 = 0.f;
#pragma unroll
        for (int nt = 0; nt < 4; ++nt) {
            sc[nt][0] = __expf(sc[nt][0] - mx0);
            sc[nt][1] = __expf(sc[nt][1] - mx0);
            sc[nt][2] = __expf(sc[nt][2] - mx1);
            sc[nt][3] = __expf(sc[nt][3] - mx1);
            s0 += sc[nt][0] + sc[nt][1];
            s1 += sc[nt][2] + sc[nt][3];
        }
        s0 += __shfl_xor_sync(0xffffffffu, s0, 1);
        s0 += __shfl_xor_sync(0xffffffffu, s0, 2);
        s1 += __shfl_xor_sync(0xffffffffu, s1, 1);
        s1 += __shfl_xor_sync(0xffffffffu, s1, 2);
        float i0v = 1.f / s0, i1v = 1.f / s1;
#pragma unroll
        for (int nt = 0; nt < 4; ++nt) {
            sc[nt][0] *= i0v; sc[nt][1] *= i0v;
            sc[nt][2] *= i1v; sc[nt][3] *= i1v;
        }
    }
    // pack attn A-fragments (hi/lo) directly from D-fragments (layouts coincide)
    uint32_t a3H[2][4], a3L[2][4];
#pragma unroll
    for (int ks = 0; ks < 2; ++ks) {
        int n0 = ks * 2, n1 = ks * 2 + 1;
        split2(sc[n0][0], sc[n0][1], a3H[ks][0], a3L[ks][0]);
        split2(sc[n0][2], sc[n0][3], a3H[ks][1], a3L[ks][1]);
        split2(sc[n1][0], sc[n1][1], a3H[ks][2], a3L[ks][2]);
        split2(sc[n1][2], sc[n1][3], a3H[ks][3], a3L[ks][3]);
    }
    __syncthreads();

    // ---- P2: Wv image -> B2 (K no longer needed) ----
    {
        const uint4* mh = (const uint4*)g_Wv_hi;
        const uint4* ml = (const uint4*)g_Wv_lo;
        uint4* dh = (uint4*)(sm + B2_HI);
        uint4* dl = (uint4*)(sm + B2_LO);
#pragma unroll
        for (int u = 0; u < 9; ++u) {
            int i = u * NT + t;
            if (i < 2176) { dh[i] = mh[i]; dl[i] = ml[i]; }
        }
    }
    __syncthreads();

    // ---- G3: raw = attn(block-diag) @ V  (K=32, B=Vt in B1) ----
    float acc3[16][4];
#pragma unroll
    for (int nt = 0; nt < 16; ++nt)
#pragma unroll
        for (int j = 0; j < 4; ++j) acc3[nt][j] = 0.f;
    g3_pass(sm, acc3, a3H, B1_HI, it, lane);
    g3_pass(sm, acc3, a3H, B1_LO, it, lane);
    g3_pass(sm, acc3, a3L, B1_HI, it, lane);

    // ---- raw frags -> A (hi/lo) ----
    {
        int r0 = it * 32 + (w & 1) * 16 + g;
#pragma unroll
        for (int nt = 0; nt < 16; ++nt) {
            int c = nt * 8 + tg * 2;
            uint32_t h, l;
            split2(acc3[nt][0], acc3[nt][1], h, l);
            sts_pair(sm, A_HI, r0, c, h);
            sts_pair(sm, A_LO, r0, c, l);
            split2(acc3[nt][2], acc3[nt][3], h, l);
            sts_pair(sm, A_HI, r0 + 8, c, h);
            sts_pair(sm, A_LO, r0 + 8, c, l);
        }
    }
    __syncthreads();

    // ---- G4: Out = raw @ Wv^T ----
    float acc4[2][8][4];
#pragma unroll
    for (int mt = 0; mt < 2; ++mt)
#pragma unroll
        for (int nt = 0; nt < 8; ++nt)
#pragma unroll
            for (int j = 0; j < 4; ++j) acc4[mt][nt][j] = 0.f;
    gemm_full(sm, acc4, mB, nB, lane, A_HI, A_LO, B2_HI, B2_LO);

    // ---- store ----
#pragma unroll
    for (int mt = 0; mt < 2; ++mt) {
        int r = mB + mt * 16 + g;
#pragma unroll
        for (int nt = 0; nt < 8; ++nt) {
            int c = nB + nt * 8 + tg * 2;
            {
                int b = r & 31, itt = r >> 5;
                float2 v = {acc4[mt][nt][0], acc4[mt][nt][1]};
                *(float2*)(Out + ((size_t)b * S_LEN + (i0 + itt)) * FD + c) = v;
            }
            {
                int r8 = r + 8;
                int b = r8 & 31, itt = r8 >> 5;
                float2 v = {acc4[mt][nt][2], acc4[mt][nt][3]};
                *(float2*)(Out + ((size_t)b * S_LEN + (i0 + itt)) * FD + c) = v;
            }
        }
    }
}

extern "C" void kernel_launch(void* const* d_in, const int* in_sizes, int n_in,
                              void* d_out, int out_size) {
    const float* q  = (const float*)d_in[0];
    const float* k  = (const float*)d_in[1];
    const float* v  = (const float*)d_in[2];
    const float* Wq = (const float*)d_in[3];
    const float* Wk = (const float*)d_in[4];
    const float* Wv = (const float*)d_in[5];
    float* out = (float*)d_out;

    prep_kernel<<<FD, FD>>>(Wq, Wk, Wv);

    cudaFuncSetAttribute(fused_attn_mma,
                         cudaFuncAttributeMaxDynamicSharedMemorySize, SMEM_BYTES);
    fused_attn_mma<<<S_LEN / TI, NT, SMEM_BYTES>>>(q, k, v, out);
}

// round 5
// speedup vs baseline: 2.2895x; 1.1793x over previous
#include <cuda_runtime.h>
#include <cuda_bf16.h>
#include <cstdint>

#define S_LEN 8192
#define FD 128
#define TI 4
#define NT 256
#define STB 272   // bytes per smem row (136 bf16); LDSM conflict-free

// ---- smem layout (byte offsets), each buffer 128*272 = 34816 B ----
#define A_HI  0u
#define A_LO  34816u
#define B1_HI 69632u
#define B1_LO 104448u
#define B2_HI 139264u
#define B2_LO 174080u
#define SMEM_BYTES 208896

// ---------------- helpers ----------------
__device__ __forceinline__ uint32_t smem_u32(const void* p) {
    return (uint32_t)__cvta_generic_to_shared(p);
}
__device__ __forceinline__ void sts_pair(char* sm, uint32_t off, int row, int col, uint32_t v) {
    *(uint32_t*)(sm + off + row * STB + col * 2) = v;
}
__device__ __forceinline__ void split2(float a, float b, uint32_t& hi, uint32_t& lo) {
    __nv_bfloat16 ha = __float2bfloat16(a), hb = __float2bfloat16(b);
    __nv_bfloat162 H; H.x = ha; H.y = hb;
    hi = *reinterpret_cast<uint32_t*>(&H);
    __nv_bfloat162 L = __floats2bfloat162_rn(a - __bfloat162float(ha), b - __bfloat162float(hb));
    lo = *reinterpret_cast<uint32_t*>(&L);
}
__device__ __forceinline__ void mma16816(float* d, const uint32_t* a, uint32_t b0, uint32_t b1) {
    asm volatile(
        "mma.sync.aligned.m16n8k16.row.col.f32.bf16.bf16.f32 "
        "{%0,%1,%2,%3}, {%4,%5,%6,%7}, {%8,%9}, {%0,%1,%2,%3};"
        : "+f"(d[0]), "+f"(d[1]), "+f"(d[2]), "+f"(d[3])
        : "r"(a[0]), "r"(a[1]), "r"(a[2]), "r"(a[3]), "r"(b0), "r"(b1));
}
__device__ __forceinline__ void ldsm4(uint32_t* r, uint32_t a) {
    asm volatile("ldmatrix.sync.aligned.m8n8.x4.shared.b16 {%0,%1,%2,%3}, [%4];"
                 : "=r"(r[0]), "=r"(r[1]), "=r"(r[2]), "=r"(r[3]) : "r"(a));
}
__device__ __forceinline__ void ldsm4t(uint32_t* r, uint32_t a) {
    asm volatile("ldmatrix.sync.aligned.m8n8.x4.trans.shared.b16 {%0,%1,%2,%3}, [%4];"
                 : "=r"(r[0]), "=r"(r[1]), "=r"(r[2]), "=r"(r[3]) : "r"(a));
}
__device__ __forceinline__ void cpa16(uint32_t dst, const void* src) {
    asm volatile("cp.async.ca.shared.global [%0], [%1], 16;" :: "r"(dst), "l"(src));
}
#define CPA_COMMIT() asm volatile("cp.async.commit_group;" ::: "memory")
#define CPA_WAIT()   asm volatile("cp.async.wait_group 0;" ::: "memory")

// ---------------- precomputed operand images (bf16 hi/lo, stride-136) ----------------
__device__ __align__(16) __nv_bfloat16 g_Mt_hi[128 * 136];
__device__ __align__(16) __nv_bfloat16 g_Mt_lo[128 * 136];
__device__ __align__(16) __nv_bfloat16 g_Wv_hi[128 * 136];
__device__ __align__(16) __nv_bfloat16 g_Wv_lo[128 * 136];

__global__ void prep_kernel(const float* __restrict__ Wq, const float* __restrict__ Wk,
                            const float* __restrict__ Wv) {
    int n = blockIdx.x, k = threadIdx.x;
    float acc = 0.f;
#pragma unroll 8
    for (int l = 0; l < FD; ++l)
        acc += Wq[l * FD + k] * Wk[l * FD + n];
    acc *= 0.08838834764831845f;  // 1/sqrt(128)
    int idx = n * 136 + k;
    __nv_bfloat16 h = __float2bfloat16(acc);
    g_Mt_hi[idx] = h;
    g_Mt_lo[idx] = __float2bfloat16(acc - __bfloat162float(h));
    float wv = Wv[n * FD + k];
    h = __float2bfloat16(wv);
    g_Wv_hi[idx] = h;
    g_Wv_lo[idx] = __float2bfloat16(wv - __bfloat162float(h));
}

// load a 128x128 fp32 tile (row r = it*32+b), split, store hi/lo stride-136
__device__ __forceinline__ void load_split(const float* __restrict__ base, uint32_t i0,
                                           char* sm, uint32_t dHi, uint32_t dLo, int t) {
    int r = t >> 1;
    int h4 = (t & 1) * 4;
    const float* row = base + ((size_t)(r & 31) * S_LEN + (i0 + (r >> 5))) * FD;
#pragma unroll
    for (int u = 0; u < 16; ++u) {
        int col = 8 * u + h4;
        float4 x = *(const float4*)(row + col);
        uint32_t h0, l0, h1, l1;
        split2(x.x, x.y, h0, l0);
        split2(x.z, x.w, h1, l1);
        sts_pair(sm, dHi, r, col, h0);
        sts_pair(sm, dHi, r, col + 2, h1);
        sts_pair(sm, dLo, r, col, l0);
        sts_pair(sm, dLo, r, col + 2, l1);
    }
}

// full 128x128x128 bf16x3 GEMM, warp tile 32m x 64n, LDSM operand fetch
__device__ __forceinline__ void gemm_full(uint32_t sbase, float acc[2][8][4],
                                          int mBase, int nBase,
                                          uint32_t aLane, uint32_t bLane,
                                          uint32_t aH, uint32_t aL,
                                          uint32_t bH, uint32_t bL) {
#pragma unroll 1
    for (int pass = 0; pass < 3; ++pass) {
        uint32_t aOff = sbase + ((pass == 2) ? aL : aH) + aLane + mBase * STB;
        uint32_t bOff = sbase + ((pass == 1) ? bL : bH) + bLane + nBase * STB;
#pragma unroll
        for (int ks = 0; ks < 8; ++ks) {
            uint32_t kb = ks * 32;
            uint32_t a[2][4];
            ldsm4(a[0], aOff + kb);
            ldsm4(a[1], aOff + 16 * STB + kb);
#pragma unroll
            for (int p = 0; p < 4; ++p) {
                uint32_t b[4];
                ldsm4(b, bOff + p * 16 * STB + kb);
                mma16816(acc[0][2 * p],     a[0], b[0], b[1]);
                mma16816(acc[0][2 * p + 1], a[0], b[2], b[3]);
                mma16816(acc[1][2 * p],     a[1], b[0], b[1]);
                mma16816(acc[1][2 * p + 1], a[1], b[2], b[3]);
            }
        }
    }
}

__global__ __launch_bounds__(NT, 1)
void fused_attn_mma(const float* __restrict__ Q, const float* __restrict__ K,
                    const float* __restrict__ V, float* __restrict__ Out) {
    extern __shared__ char sm[];
    const uint32_t sbase = smem_u32(sm);
    const int t = threadIdx.x, lane = t & 31, w = t >> 5;
    const int g = lane >> 2, tg = lane & 3;
    const uint32_t i0 = blockIdx.x * TI;

    // LDSM per-lane address components
    const uint32_t aLane = (uint32_t)(lane & 15) * STB + (uint32_t)(lane >> 4) * 16;
    const uint32_t bLane = (uint32_t)((lane & 7) + ((lane & 16) >> 1)) * STB + (uint32_t)(lane & 8) * 2;
    const uint32_t tLane = (uint32_t)((lane & 7) + (lane & 8)) * STB + (uint32_t)(lane >> 4) * 16;

    // ---- P0: Mt -> B1 (cp.async), Q -> A, K -> B2 ----
    {
        const char* mh = (const char*)g_Mt_hi;
        const char* ml = (const char*)g_Mt_lo;
#pragma unroll
        for (int u = 0; u < 9; ++u) {
            int i = u * NT + t;
            if (i < 2176) {
                cpa16(sbase + B1_HI + i * 16, mh + i * 16);
                cpa16(sbase + B1_LO + i * 16, ml + i * 16);
            }
        }
        CPA_COMMIT();
    }
    load_split(Q, i0, sm, A_HI, A_LO, t);
    load_split(K, i0, sm, B2_HI, B2_LO, t);
    CPA_WAIT();
    __syncthreads();

    // ---- G1: QM = Q @ Mt^T ----
    const int mB = (w >> 1) * 32, nB = (w & 1) * 64;
    float acc[2][8][4];
#pragma unroll
    for (int mt = 0; mt < 2; ++mt)
#pragma unroll
        for (int nt = 0; nt < 8; ++nt)
#pragma unroll
            for (int j = 0; j < 4; ++j) acc[mt][nt][j] = 0.f;
    gemm_full(sbase, acc, mB, nB, aLane, bLane, A_HI, A_LO, B1_HI, B1_LO);
    __syncthreads();

    // ---- P1: QM frags -> A (hi/lo); V (natural layout) -> B1 ----
#pragma unroll
    for (int mt = 0; mt < 2; ++mt)
#pragma unroll
        for (int nt = 0; nt < 8; ++nt) {
            int r = mB + mt * 16 + g, c = nB + nt * 8 + tg * 2;
            uint32_t h, l;
            split2(acc[mt][nt][0], acc[mt][nt][1], h, l);
            sts_pair(sm, A_HI, r, c, h);
            sts_pair(sm, A_LO, r, c, l);
            split2(acc[mt][nt][2], acc[mt][nt][3], h, l);
            sts_pair(sm, A_HI, r + 8, c, h);
            sts_pair(sm, A_LO, r + 8, c, l);
        }
    load_split(V, i0, sm, B1_HI, B1_LO, t);
    __syncthreads();

    // ---- G2: diagonal scores (warp strip: 16 rows x 32 cols) ----
    const int it = w >> 1;
    const int mB2 = it * 32 + (w & 1) * 16;
    const int nB2 = it * 32;
    float sc[4][4];
#pragma unroll
    for (int nt = 0; nt < 4; ++nt)
#pragma unroll
        for (int j = 0; j < 4; ++j) sc[nt][j] = 0.f;
#pragma unroll 1
    for (int pass = 0; pass < 3; ++pass) {
        uint32_t aOff = sbase + ((pass == 2) ? A_LO : A_HI) + aLane + mB2 * STB;
        uint32_t bOff = sbase + ((pass == 1) ? B2_LO : B2_HI) + bLane + nB2 * STB;
#pragma unroll
        for (int ks = 0; ks < 8; ++ks) {
            uint32_t kb = ks * 32;
            uint32_t a[4];
            ldsm4(a, aOff + kb);
            uint32_t b0[4], b1[4];
            ldsm4(b0, bOff + kb);
            ldsm4(b1, bOff + 16 * STB + kb);
            mma16816(sc[0], a, b0[0], b0[1]);
            mma16816(sc[1], a, b0[2], b0[3]);
            mma16816(sc[2], a, b1[0], b1[1]);
            mma16816(sc[3], a, b1[2], b1[3]);
        }
    }

    // ---- softmax over 32 cols (rows g and g+8 of this warp strip) ----
    {
        float mx0 = -1e30f, mx1 = -1e30f;
#pragma unroll
        for (int nt = 0; nt < 4; ++nt) {
            mx0 = fmaxf(mx0, fmaxf(sc[nt][0], sc[nt][1]));
            mx1 = fmaxf(mx1, fmaxf(sc[nt][2], sc[nt][3]));
        }
        mx0 = fmaxf(mx0, __shfl_xor_sync(0xffffffffu, mx0, 1));
        mx0 = fmaxf(mx0, __shfl_xor_sync(0xffffffffu, mx0, 2));
        mx1 = fmaxf(mx1, __shfl_xor_sync(0xffffffffu, mx1, 1));
        mx1 = fmaxf(mx1, __shfl_xor_sync(0xffffffffu, mx1, 2));
        float s0 = 0.f, s1 = 0.f;
#pragma unroll
        for (int nt = 0; nt < 4; ++nt) {
            sc[nt][0] = __expf(sc[nt][0] - mx0);
            sc[nt][1] = __expf(sc[nt][1] - mx0);
            sc[nt][2] = __expf(sc[nt][2] - mx1);
            sc[nt][3] = __expf(sc[nt][3] - mx1);
            s0 += sc[nt][0] + sc[nt][1];
            s1 += sc[nt][2] + sc[nt][3];
        }
        s0 += __shfl_xor_sync(0xffffffffu, s0, 1);
        s0 += __shfl_xor_sync(0xffffffffu, s0, 2);
        s1 += __shfl_xor_sync(0xffffffffu, s1, 1);
        s1 += __shfl_xor_sync(0xffffffffu, s1, 2);
        float i0v = 1.f / s0, i1v = 1.f / s1;
#pragma unroll
        for (int nt = 0; nt < 4; ++nt) {
            sc[nt][0] *= i0v; sc[nt][1] *= i0v;
            sc[nt][2] *= i1v; sc[nt][3] *= i1v;
        }
    }
    // attn A-fragments (hi/lo) directly from D-fragments (layouts coincide)
    uint32_t a3H[2][4], a3L[2][4];
#pragma unroll
    for (int ks = 0; ks < 2; ++ks) {
        int n0 = ks * 2, n1 = ks * 2 + 1;
        split2(sc[n0][0], sc[n0][1], a3H[ks][0], a3L[ks][0]);
        split2(sc[n0][2], sc[n0][3], a3H[ks][1], a3L[ks][1]);
        split2(sc[n1][0], sc[n1][1], a3H[ks][2], a3L[ks][2]);
        split2(sc[n1][2], sc[n1][3], a3H[ks][3], a3L[ks][3]);
    }
    __syncthreads();   // everyone done reading A (QM) and B2 (K)

    // ---- Wv -> B2 via cp.async, overlapped with G3 ----
    {
        const char* wh = (const char*)g_Wv_hi;
        const char* wl = (const char*)g_Wv_lo;
#pragma unroll
        for (int u = 0; u < 9; ++u) {
            int i = u * NT + t;
            if (i < 2176) {
                cpa16(sbase + B2_HI + i * 16, wh + i * 16);
                cpa16(sbase + B2_LO + i * 16, wl + i * 16);
            }
        }
        CPA_COMMIT();
    }

    // ---- G3: raw = attn(block-diag) @ V   (B via ldmatrix.trans on natural V) ----
    float acc3[16][4];
#pragma unroll
    for (int nt = 0; nt < 16; ++nt)
#pragma unroll
        for (int j = 0; j < 4; ++j) acc3[nt][j] = 0.f;
#pragma unroll 1
    for (int pass = 0; pass < 3; ++pass) {
        uint32_t bOff = sbase + ((pass == 1) ? B1_LO : B1_HI) + tLane + (uint32_t)(it * 32) * STB;
#pragma unroll
        for (int ks = 0; ks < 2; ++ks) {
            const uint32_t* av = (pass == 2) ? a3L[ks] : a3H[ks];
#pragma unroll
            for (int p = 0; p < 8; ++p) {
                uint32_t b[4];
                ldsm4t(b, bOff + (uint32_t)(ks * 16) * STB + p * 32);
                mma16816(acc3[2 * p],     av, b[0], b[1]);
                mma16816(acc3[2 * p + 1], av, b[2], b[3]);
            }
        }
    }

    // ---- raw frags -> A (hi/lo) ----
    {
        int r0 = it * 32 + (w & 1) * 16 + g;
#pragma unroll
        for (int nt = 0; nt < 16; ++nt) {
            int c = nt * 8 + tg * 2;
            uint32_t h, l;
            split2(acc3[nt][0], acc3[nt][1], h, l);
            sts_pair(sm, A_HI, r0, c, h);
            sts_pair(sm, A_LO, r0, c, l);
            split2(acc3[nt][2], acc3[nt][3], h, l);
            sts_pair(sm, A_HI, r0 + 8, c, h);
            sts_pair(sm, A_LO, r0 + 8, c, l);
        }
    }
    CPA_WAIT();
    __syncthreads();

    // ---- G4: Out = raw @ Wv^T ----
    float acc4[2][8][4];
#pragma unroll
    for (int mt = 0; mt < 2; ++mt)
#pragma unroll
        for (int nt = 0; nt < 8; ++nt)
#pragma unroll
            for (int j = 0; j < 4; ++j) acc4[mt][nt][j] = 0.f;
    gemm_full(sbase, acc4, mB, nB, aLane, bLane, A_HI, A_LO, B2_HI, B2_LO);

    // ---- store ----
#pragma unroll
    for (int mt = 0; mt < 2; ++mt) {
        int r = mB + mt * 16 + g;
#pragma unroll
        for (int nt = 0; nt < 8; ++nt) {
            int c = nB + nt * 8 + tg * 2;
            {
                int b = r & 31, itt = r >> 5;
                float2 v = {acc4[mt][nt][0], acc4[mt][nt][1]};
                *(float2*)(Out + ((size_t)b * S_LEN + (i0 + itt)) * FD + c) = v;
            }
            {
                int r8 = r + 8;
                int b = r8 & 31, itt = r8 >> 5;
                float2 v = {acc4[mt][nt][2], acc4[mt][nt][3]};
                *(float2*)(Out + ((size_t)b * S_LEN + (i0 + itt)) * FD + c) = v;
            }
        }
    }
}

extern "C" void kernel_launch(void* const* d_in, const int* in_sizes, int n_in,
                              void* d_out, int out_size) {
    const float* q  = (const float*)d_in[0];
    const float* k  = (const float*)d_in[1];
    const float* v  = (const float*)d_in[2];
    const float* Wq = (const float*)d_in[3];
    const float* Wk = (const float*)d_in[4];
    const float* Wv = (const float*)d_in[5];
    float* out = (float*)d_out;

    prep_kernel<<<FD, FD>>>(Wq, Wk, Wv);

    cudaFuncSetAttribute(fused_attn_mma,
                         cudaFuncAttributeMaxDynamicSharedMemorySize, SMEM_BYTES);
    fused_attn_mma<<<S_LEN / TI, NT, SMEM_BYTES>>>(q, k, v, out);
}